// round 11
// baseline (speedup 1.0000x reference)
#include <cuda_runtime.h>
#include <cuda_bf16.h>
#include <stdint.h>

#define BB 2
#define NN 2048
#define EE 1024
#define HH 16
#define DD 64
#define MTOT (BB * NN)

// ---------------------------------------------------------------------------
// Scratch
// ---------------------------------------------------------------------------
__device__ float g_q [BB * HH * NN * DD];
__device__ float g_k [BB * HH * NN * DD];
__device__ float g_v [BB * HH * NN * DD];
__device__ float g_ao[(size_t)MTOT * EE];

// ---------------------------------------------------------------------------
// Helpers
// ---------------------------------------------------------------------------
__device__ __forceinline__ void bfsplit(float x, float& h, float& l) {
    h = __bfloat162float(__float2bfloat16(x));
    l = x - h;
}

__device__ __forceinline__ uint32_t packbf(float a, float b) {
    __nv_bfloat162 t = __floats2bfloat162_rn(a, b);
    return *reinterpret_cast<uint32_t*>(&t);
}

// ldmatrix x4 (b16, non-transposed)
__device__ __forceinline__ void ldsm4(uint32_t& r0, uint32_t& r1, uint32_t& r2, uint32_t& r3,
                                      uint32_t addr) {
    asm volatile("ldmatrix.sync.aligned.m8n8.x4.shared.b16 {%0,%1,%2,%3}, [%4];"
        : "=r"(r0), "=r"(r1), "=r"(r2), "=r"(r3) : "r"(addr));
}

// ldmatrix x4 transposed
__device__ __forceinline__ void ldsm4t(uint32_t& r0, uint32_t& r1, uint32_t& r2, uint32_t& r3,
                                       uint32_t addr) {
    asm volatile("ldmatrix.sync.aligned.m8n8.x4.trans.shared.b16 {%0,%1,%2,%3}, [%4];"
        : "=r"(r0), "=r"(r1), "=r"(r2), "=r"(r3) : "r"(addr));
}

// bf16 m16n8k16
__device__ __forceinline__ void mmabf(float& c0, float& c1, float& c2, float& c3,
                                      uint32_t a0, uint32_t a1, uint32_t a2, uint32_t a3,
                                      uint32_t b0, uint32_t b1) {
    asm volatile(
        "mma.sync.aligned.m16n8k16.row.col.f32.bf16.bf16.f32 "
        "{%0,%1,%2,%3}, {%4,%5,%6,%7}, {%8,%9}, {%0,%1,%2,%3};\n"
        : "+f"(c0), "+f"(c1), "+f"(c2), "+f"(c3)
        : "r"(a0), "r"(a1), "r"(a2), "r"(a3), "r"(b0), "r"(b1));
}

__device__ __forceinline__ void mmabf_3x(float* c,
                                         const uint32_t* ah, const uint32_t* al,
                                         const uint32_t* bh, const uint32_t* bl) {
    mmabf(c[0], c[1], c[2], c[3], al[0], al[1], al[2], al[3], bh[0], bh[1]);
    mmabf(c[0], c[1], c[2], c[3], ah[0], ah[1], ah[2], ah[3], bl[0], bl[1]);
    mmabf(c[0], c[1], c[2], c[3], ah[0], ah[1], ah[2], ah[3], bh[0], bh[1]);
}

// ---------------------------------------------------------------------------
// 3xbf16 GEMM (unchanged from R8): Y[m,e] = X[m,:] . W[e,:] + bias[e]
// ---------------------------------------------------------------------------
template<int SCATTER>
__global__ __launch_bounds__(256, 2)
void gemm_bf16(const float* __restrict__ X,
               const float* __restrict__ W,
               const float* __restrict__ bias,
               float* __restrict__ Y)
{
    extern __shared__ uint32_t gsm[];
    uint32_t* Asm = gsm;                // [128][32]: hi cols 0-15, lo cols 16-31
    uint32_t* Bsm = Asm + 128 * 32;     // [128][32]

    const int tid  = threadIdx.x;
    const int lane = tid & 31;
    const int warp = tid >> 5;
    const int wm = warp >> 2, wn = warp & 3;
    const int g = lane >> 2, t4 = lane & 3;
    const int m0 = blockIdx.y * 128, n0 = blockIdx.x * 128;

    const int aRow = tid >> 3, aK4 = tid & 7;
    const int bN = tid >> 1, bKh = tid & 1;

    const int sel = lane >> 3;
    const int lrow = lane & 7;
    const int swl = lrow << 2;
    const int aoff = (sel & 1) * 8 + lrow;
    const int akoff = (sel >> 1) * 4;
    const int bnt = sel >> 1;
    const int bkoff = (sel & 1) * 4;

    const uint32_t a_base = (uint32_t)__cvta_generic_to_shared(Asm);
    const uint32_t b_base = (uint32_t)__cvta_generic_to_shared(Bsm);

    float acc[4][4][4];
    #pragma unroll
    for (int i = 0; i < 4; ++i)
        #pragma unroll
        for (int j = 0; j < 4; ++j)
            #pragma unroll
            for (int c = 0; c < 4; ++c) acc[i][j][c] = 0.f;

    const float* Xb = X + (size_t)m0 * EE;
    const float* Wb = W + (size_t)n0 * EE;

    for (int kt = 0; kt < EE; kt += 32) {
        __syncthreads();
        #pragma unroll
        for (int i = 0; i < 4; ++i) {
            const int m = aRow + 32 * i;
            float4 v = *(const float4*)(Xb + (size_t)m * EE + kt + aK4 * 4);
            float h0, l0, h1, l1, h2, l2, h3, l3;
            bfsplit(v.x, h0, l0); bfsplit(v.y, h1, l1);
            bfsplit(v.z, h2, l2); bfsplit(v.w, h3, l3);
            const int sw = (m & 7) << 2;
            *(uint2*)(&Asm[m * 32 + ((aK4 * 2) ^ sw)]) =
                make_uint2(packbf(h0, h1), packbf(h2, h3));
            *(uint2*)(&Asm[m * 32 + ((16 + aK4 * 2) ^ sw)]) =
                make_uint2(packbf(l0, l1), packbf(l2, l3));
        }
        #pragma unroll
        for (int j = 0; j < 4; ++j) {
            const int kq = 2 * j + bKh;
            float4 v = *(const float4*)(Wb + (size_t)bN * EE + kt + kq * 4);
            float h0, l0, h1, l1, h2, l2, h3, l3;
            bfsplit(v.x, h0, l0); bfsplit(v.y, h1, l1);
            bfsplit(v.z, h2, l2); bfsplit(v.w, h3, l3);
            const int sw = (bN & 7) << 2;
            *(uint2*)(&Bsm[bN * 32 + ((kq * 2) ^ sw)]) =
                make_uint2(packbf(h0, h1), packbf(h2, h3));
            *(uint2*)(&Bsm[bN * 32 + ((16 + kq * 2) ^ sw)]) =
                make_uint2(packbf(l0, l1), packbf(l2, l3));
        }
        __syncthreads();

        #pragma unroll
        for (int kk = 0; kk < 2; ++kk) {
            const int c8 = kk * 8;
            uint32_t bh[4][2], bl[4][2];
            #pragma unroll
            for (int p = 0; p < 2; ++p) {
                const int brow = wn * 32 + (p * 2 + bnt) * 8 + lrow;
                const uint32_t ab = b_base + (brow * 32) * 4;
                ldsm4(bh[p*2][0], bh[p*2][1], bh[p*2+1][0], bh[p*2+1][1],
                      ab + (((c8 + bkoff) ^ swl) << 2));
                ldsm4(bl[p*2][0], bl[p*2][1], bl[p*2+1][0], bl[p*2+1][1],
                      ab + (((16 + c8 + bkoff) ^ swl) << 2));
            }
            #pragma unroll
            for (int mt = 0; mt < 4; ++mt) {
                const int arow = wm * 64 + mt * 16 + aoff;
                const uint32_t aa = a_base + (arow * 32) * 4;
                uint32_t ah[4], al[4];
                ldsm4(ah[0], ah[1], ah[2], ah[3], aa + (((c8 + akoff) ^ swl) << 2));
                ldsm4(al[0], al[1], al[2], al[3], aa + (((16 + c8 + akoff) ^ swl) << 2));
                #pragma unroll
                for (int nt = 0; nt < 4; ++nt)
                    mmabf_3x(acc[mt][nt], ah, al, bh[nt], bl[nt]);
            }
        }
    }

    #pragma unroll
    for (int mt = 0; mt < 4; ++mt) {
        const int r0 = m0 + wm * 64 + mt * 16 + g;
        #pragma unroll
        for (int nt = 0; nt < 4; ++nt) {
            const int c = n0 + wn * 32 + nt * 8 + 2 * t4;
            const float bv0 = bias[c], bv1 = bias[c + 1];
            float2 v0 = make_float2(acc[mt][nt][0] + bv0, acc[mt][nt][1] + bv1);
            float2 v1 = make_float2(acc[mt][nt][2] + bv0, acc[mt][nt][3] + bv1);
            if (SCATTER) {
                const int h = c >> 6, d = c & 63;
                const int b0i = r0 >> 11, n0i = r0 & (NN - 1);
                *(float2*)(&Y[((((size_t)b0i * HH + h) * NN) + n0i) * DD + d]) = v0;
                const int r1 = r0 + 8;
                const int b1i = r1 >> 11, n1i = r1 & (NN - 1);
                *(float2*)(&Y[((((size_t)b1i * HH + h) * NN) + n1i) * DD + d]) = v1;
            } else {
                *(float2*)(&Y[(size_t)r0 * EE + c]) = v0;
                *(float2*)(&Y[(size_t)(r0 + 8) * EE + c]) = v1;
            }
        }
    }
}

// ---------------------------------------------------------------------------
// Flash attention. BQ=64, BKV=64, 8 warps (2x4). All-bf16 tensor path:
// mma1 (3xbf16, ldmatrix): S^T[kv][q] = K . Q^T
// softmax col-wise over kv (online m/l); writes P as packed bf16 hi/lo [q][kv2]
// mma2 (3xbf16): O[q][d] += P . V ; A=P via ldmatrix, B=V via ldmatrix.trans
// quirk: /sqrt(E)=32 applied post-softmax in epilogue
// ---------------------------------------------------------------------------
__global__ __launch_bounds__(256)
void flash_bf16(const float* __restrict__ qb,
                const float* __restrict__ kb,
                const float* __restrict__ vb,
                float* __restrict__ out)
{
    extern __shared__ char smraw[];
    uint32_t* Qh = (uint32_t*)smraw;       // [64 q][32 d2], swizzle (q&7)<<2
    uint32_t* Ql = Qh + 64 * 32;
    uint32_t* Kh = Ql + 64 * 32;           // [64 kv][32 d2]
    uint32_t* Kl = Kh + 64 * 32;
    uint32_t* Vh = Kl + 64 * 32;           // [64 kv][32 d2] (same layout as K)
    uint32_t* Vl = Vh + 64 * 32;
    uint32_t* Ph = Vl + 64 * 32;           // [64 q][32 kv2], swizzle (q&7)<<2
    uint32_t* Pl = Ph + 64 * 32;
    float*    St = (float*)(Pl + 64 * 32); // [kv][q ^ ((kv&3)<<3)]
    float* mrow = St + 64 * 64;
    float* lrow = mrow + 64;
    float* arow = lrow + 64;
    float* pmax = arow + 64;               // [4][64]
    float* psum = pmax + 256;              // [4][64]

    const int tid  = threadIdx.x;
    const int lane = tid & 31;
    const int warp = tid >> 5;
    const int wm = warp >> 2, wn = warp & 3;
    const int g = lane >> 2, t4 = lane & 3;

    const int q0 = blockIdx.x * 64;
    const int bh = blockIdx.y;
    const int b  = bh >> 4;
    const int h  = bh & (HH - 1);

    // ldmatrix per-lane geometry
    const int sel = lane >> 3;
    const int lrowm = lane & 7;
    const int swl = lrowm << 2;
    const int aoff = (sel & 1) * 8 + lrowm;      // A tiles (rows of m dim)
    const int akoff = (sel >> 1) * 4;            // A: k-half (u32)
    const int bnt = sel >> 1;                    // B tiles (non-trans)
    const int bkoff = (sel & 1) * 4;

    const uint32_t qh_base = (uint32_t)__cvta_generic_to_shared(Qh);
    const uint32_t ql_base = (uint32_t)__cvta_generic_to_shared(Ql);
    const uint32_t kh_base = (uint32_t)__cvta_generic_to_shared(Kh);
    const uint32_t kl_base = (uint32_t)__cvta_generic_to_shared(Kl);
    const uint32_t vh_base = (uint32_t)__cvta_generic_to_shared(Vh);
    const uint32_t vl_base = (uint32_t)__cvta_generic_to_shared(Vl);
    const uint32_t ph_base = (uint32_t)__cvta_generic_to_shared(Ph);
    const uint32_t pl_base = (uint32_t)__cvta_generic_to_shared(Pl);

    if (tid < 64) { mrow[tid] = -1e30f; lrow[tid] = 0.f; }

    // Q load + bf16 hi/lo split (once per block)
    const float* Qg = qb + ((size_t)bh * NN + q0) * DD;
    const int d4 = tid & 15, row0 = tid >> 4;
    #pragma unroll
    for (int i = 0; i < 4; ++i) {
        const int q = row0 + 16 * i;
        float4 v = *(const float4*)(Qg + (size_t)q * DD + d4 * 4);
        float h0, l0, h1, l1, h2, l2, h3, l3;
        bfsplit(v.x, h0, l0); bfsplit(v.y, h1, l1);
        bfsplit(v.z, h2, l2); bfsplit(v.w, h3, l3);
        const int idx = q * 32 + ((d4 * 2) ^ ((q & 7) << 2));
        *(uint2*)(&Qh[idx]) = make_uint2(packbf(h0, h1), packbf(h2, h3));
        *(uint2*)(&Ql[idx]) = make_uint2(packbf(l0, l1), packbf(l2, l3));
    }

    float oacc[2][2][4];
    #pragma unroll
    for (int i = 0; i < 2; ++i)
        #pragma unroll
        for (int j = 0; j < 2; ++j)
            #pragma unroll
            for (int c = 0; c < 4; ++c) oacc[i][j][c] = 0.f;

    const float* Kg = kb + (size_t)bh * NN * DD;
    const float* Vg = vb + (size_t)bh * NN * DD;

    for (int kv0 = 0; kv0 < NN; kv0 += 64) {
        __syncthreads();
        #pragma unroll
        for (int i = 0; i < 4; ++i) {
            const int kv = row0 + 16 * i;
            float4 kv4 = *(const float4*)(Kg + (size_t)(kv0 + kv) * DD + d4 * 4);
            float4 vv4 = *(const float4*)(Vg + (size_t)(kv0 + kv) * DD + d4 * 4);
            float h0, l0, h1, l1, h2, l2, h3, l3;
            const int kidx = kv * 32 + ((d4 * 2) ^ ((kv & 7) << 2));
            bfsplit(kv4.x, h0, l0); bfsplit(kv4.y, h1, l1);
            bfsplit(kv4.z, h2, l2); bfsplit(kv4.w, h3, l3);
            *(uint2*)(&Kh[kidx]) = make_uint2(packbf(h0, h1), packbf(h2, h3));
            *(uint2*)(&Kl[kidx]) = make_uint2(packbf(l0, l1), packbf(l2, l3));
            bfsplit(vv4.x, h0, l0); bfsplit(vv4.y, h1, l1);
            bfsplit(vv4.z, h2, l2); bfsplit(vv4.w, h3, l3);
            *(uint2*)(&Vh[kidx]) = make_uint2(packbf(h0, h1), packbf(h2, h3));
            *(uint2*)(&Vl[kidx]) = make_uint2(packbf(l0, l1), packbf(l2, l3));
        }
        __syncthreads();

        // mma1: S^T = K . Q^T  (3xbf16, ldmatrix fragments)
        float sacc[2][2][4];
        #pragma unroll
        for (int i = 0; i < 2; ++i)
            #pragma unroll
            for (int j = 0; j < 2; ++j)
                #pragma unroll
                for (int c = 0; c < 4; ++c) sacc[i][j][c] = 0.f;

        #pragma unroll
        for (int kk = 0; kk < 4; ++kk) {
            const int c8 = kk * 8;
            uint32_t bh_[2][2], bl_[2][2];
            {
                const int brow = wn * 16 + bnt * 8 + lrowm;
                const uint32_t off = ((c8 + bkoff) ^ swl) << 2;
                ldsm4(bh_[0][0], bh_[0][1], bh_[1][0], bh_[1][1],
                      qh_base + (brow * 32) * 4 + off);
                ldsm4(bl_[0][0], bl_[0][1], bl_[1][0], bl_[1][1],
                      ql_base + (brow * 32) * 4 + off);
            }
            #pragma unroll
            for (int mt = 0; mt < 2; ++mt) {
                const int arow = wm * 32 + mt * 16 + aoff;
                const uint32_t off = ((c8 + akoff) ^ swl) << 2;
                uint32_t ah[4], al[4];
                ldsm4(ah[0], ah[1], ah[2], ah[3], kh_base + (arow * 32) * 4 + off);
                ldsm4(al[0], al[1], al[2], al[3], kl_base + (arow * 32) * 4 + off);
                #pragma unroll
                for (int nt = 0; nt < 2; ++nt)
                    mmabf_3x(sacc[mt][nt], ah, al, bh_[nt], bl_[nt]);
            }
        }
        #pragma unroll
        for (int mt = 0; mt < 2; ++mt) {
            const int kvr = wm * 32 + mt * 16 + g;
            #pragma unroll
            for (int nt = 0; nt < 2; ++nt) {
                const int qc = wn * 16 + nt * 8 + 2 * t4;
                *(float2*)(&St[kvr * 64 + (qc ^ ((kvr & 3) << 3))]) =
                    make_float2(sacc[mt][nt][0], sacc[mt][nt][1]);
                *(float2*)(&St[(kvr + 8) * 64 + (qc ^ (((kvr + 8) & 3) << 3))]) =
                    make_float2(sacc[mt][nt][2], sacc[mt][nt][3]);
            }
        }
        __syncthreads();

        // online softmax over kv (columns of S^T); write P packed bf16 hi/lo
        {
            const int q = tid & 63, kvg = tid >> 6;
            float sv[16];
            float mloc = -1e30f;
            #pragma unroll
            for (int r = 0; r < 16; ++r) {
                const int kv = kvg * 16 + r;
                sv[r] = St[kv * 64 + (q ^ ((kv & 3) << 3))];
                mloc = fmaxf(mloc, sv[r]);
            }
            pmax[kvg * 64 + q] = mloc;
            __syncthreads();
            const float mold = mrow[q];
            const float mnew = fmaxf(mold,
                fmaxf(fmaxf(pmax[q], pmax[64 + q]), fmaxf(pmax[128 + q], pmax[192 + q])));
            float sloc = 0.f;
            #pragma unroll
            for (int rp = 0; rp < 8; ++rp) {
                const float p0 = __expf(sv[rp * 2] - mnew);
                const float p1 = __expf(sv[rp * 2 + 1] - mnew);
                sloc += p0 + p1;
                float h0, l0, h1, l1;
                bfsplit(p0, h0, l0);
                bfsplit(p1, h1, l1);
                const int col = (kvg * 8 + rp) ^ ((q & 7) << 2);
                Ph[q * 32 + col] = packbf(h0, h1);
                Pl[q * 32 + col] = packbf(l0, l1);
            }
            psum[kvg * 64 + q] = sloc;
            __syncthreads();
            if (kvg == 0) {
                const float alpha = __expf(mold - mnew);
                lrow[q] = lrow[q] * alpha + psum[q] + psum[64 + q] + psum[128 + q] + psum[192 + q];
                mrow[q] = mnew;
                arow[q] = alpha;
            }
            __syncthreads();
        }

        // rescale O accumulators
        #pragma unroll
        for (int mt = 0; mt < 2; ++mt) {
            const int qr = wm * 32 + mt * 16 + g;
            const float al0 = arow[qr], al1 = arow[qr + 8];
            #pragma unroll
            for (int nt = 0; nt < 2; ++nt) {
                oacc[mt][nt][0] *= al0; oacc[mt][nt][1] *= al0;
                oacc[mt][nt][2] *= al1; oacc[mt][nt][3] *= al1;
            }
        }

        // mma2: O += P . V  (3xbf16; A = P ldmatrix, B = V ldmatrix.trans)
        #pragma unroll
        for (int kk = 0; kk < 4; ++kk) {
            uint32_t bvh[2][2], bvl[2][2];
            {
                // trans B: rows = kv (k dim), 16B segment = d tile (n dim)
                const int kvr = kk * 16 + (sel & 1) * 8 + lrowm;
                const uint32_t off = (((wn * 8 + (sel >> 1) * 4) ^ (lrowm << 2)) << 2);
                ldsm4t(bvh[0][0], bvh[0][1], bvh[1][0], bvh[1][1],
                       vh_base + (kvr * 32) * 4 + off);
                ldsm4t(bvl[0][0], bvl[0][1], bvl[1][0], bvl[1][1],
                       vl_base + (kvr * 32) * 4 + off);
            }
            #pragma unroll
            for (int mt = 0; mt < 2; ++mt) {
                const int qrow = wm * 32 + mt * 16 + aoff;
                const uint32_t off = ((kk * 8 + akoff) ^ swl) << 2;
                uint32_t ph[4], pl[4];
                ldsm4(ph[0], ph[1], ph[2], ph[3], ph_base + (qrow * 32) * 4 + off);
                ldsm4(pl[0], pl[1], pl[2], pl[3], pl_base + (qrow * 32) * 4 + off);
                #pragma unroll
                for (int nt = 0; nt < 2; ++nt)
                    mmabf_3x(oacc[mt][nt], ph, pl, bvh[nt], bvl[nt]);
            }
        }
    }

    // epilogue: /l, /sqrt(E)=32, merge heads
    #pragma unroll
    for (int mt = 0; mt < 2; ++mt) {
        const int qr = wm * 32 + mt * 16 + g;
        const float inv0 = 1.f / (lrow[qr] * 32.f);
        const float inv1 = 1.f / (lrow[qr + 8] * 32.f);
        #pragma unroll
        for (int nt = 0; nt < 2; ++nt) {
            const int dc = wn * 16 + nt * 8 + 2 * t4;
            *(float2*)(&out[((size_t)b * NN + q0 + qr) * EE + h * DD + dc]) =
                make_float2(oacc[mt][nt][0] * inv0, oacc[mt][nt][1] * inv0);
            *(float2*)(&out[((size_t)b * NN + q0 + qr + 8) * EE + h * DD + dc]) =
                make_float2(oacc[mt][nt][2] * inv1, oacc[mt][nt][3] * inv1);
        }
    }
}

// ---------------------------------------------------------------------------
// Launcher
// ---------------------------------------------------------------------------
extern "C" void kernel_launch(void* const* d_in, const int* in_sizes, int n_in,
                              void* d_out, int out_size)
{
    const float* queries = (const float*)d_in[0];
    const float* keys    = (const float*)d_in[1];
    const float* values  = (const float*)d_in[2];
    const float* Wq = (const float*)d_in[3];
    const float* bq = (const float*)d_in[4];
    const float* Wk = (const float*)d_in[5];
    const float* bk = (const float*)d_in[6];
    const float* Wv = (const float*)d_in[7];
    const float* bv = (const float*)d_in[8];
    const float* Wp = (const float*)d_in[9];
    const float* bp = (const float*)d_in[10];
    float* out = (float*)d_out;

    float *pq, *pk, *pv, *pao;
    cudaGetSymbolAddress((void**)&pq,  g_q);
    cudaGetSymbolAddress((void**)&pk,  g_k);
    cudaGetSymbolAddress((void**)&pv,  g_v);
    cudaGetSymbolAddress((void**)&pao, g_ao);

    const int gemm_smem = 2 * 128 * 32 * (int)sizeof(uint32_t); // 32768
    cudaFuncSetAttribute(gemm_bf16<1>,
                         cudaFuncAttributeMaxDynamicSharedMemorySize, gemm_smem);
    cudaFuncSetAttribute(gemm_bf16<0>,
                         cudaFuncAttributeMaxDynamicSharedMemorySize, gemm_smem);

    const dim3 gemm_grid(EE / 128, MTOT / 128);   // (8, 32)
    gemm_bf16<1><<<gemm_grid, 256, gemm_smem>>>(queries, Wq, bq, pq);
    gemm_bf16<1><<<gemm_grid, 256, gemm_smem>>>(keys,    Wk, bk, pk);
    gemm_bf16<1><<<gemm_grid, 256, gemm_smem>>>(values,  Wv, bv, pv);

    // Qh/Ql/Kh/Kl/Vh/Vl/Ph/Pl: 8*64*32 u32; St: 64*64 f32; rows: 704 f32
    const int fa_smem = (8 * 64 * 32 + 64 * 64) * 4 + (3 * 64 + 2 * 256) * 4; // 84736
    cudaFuncSetAttribute(flash_bf16,
                         cudaFuncAttributeMaxDynamicSharedMemorySize, fa_smem);
    const dim3 fa_grid(NN / 64, BB * HH);         // (32, 32)
    flash_bf16<<<fa_grid, 256, fa_smem>>>(pq, pk, pv, pao);

    gemm_bf16<0><<<gemm_grid, 256, gemm_smem>>>(pao, Wp, bp, out);
}